// round 4
// baseline (speedup 1.0000x reference)
#include <cuda_runtime.h>
#include <cuda_fp16.h>
#include <cstdint>

// out[M,N] = X[M,K] @ Wq[N,K]^T, Wq = sign(W)*max(scales,1e-8), groups of 128 along K
#define MDIM 8192
#define NDIM 4096
#define KDIM 4096

#define TM 128
#define TN 256
#define TKH 128                      // halves per K stage (two 64-half panels) == one scale group
#define NSTAGE 2
#define KSTAGES (KDIM / TKH)         // 32

#define A_BYTES (TM * 256)           // 32768 per stage
#define B_BYTES (TN * 256)           // 65536 per stage
#define STAGE_BYTES (A_BYTES + B_BYTES)        // 98304
#define SMEM_BYTES (NSTAGE * STAGE_BYTES)      // 196608

// Pre-swizzled tile-major operand images (exact smem byte image per (tile,stage)).
__device__ __align__(16) __half g_Xh[(size_t)MDIM * KDIM];   // 64 MB
__device__ __align__(16) __half g_Wh[(size_t)NDIM * KDIM];   // 32 MB

__device__ __forceinline__ uint32_t smem_u32(const void* p) {
    uint32_t a;
    asm("{ .reg .u64 t; cvta.to.shared.u64 t, %1; cvt.u32.u64 %0, t; }" : "=r"(a) : "l"(p));
    return a;
}

#define LDMATRIX_X4(r0, r1, r2, r3, addr)                                        \
    asm volatile("ldmatrix.sync.aligned.m8n8.x4.shared.b16 {%0,%1,%2,%3}, [%4];" \
                 : "=r"(r0), "=r"(r1), "=r"(r2), "=r"(r3) : "r"(addr))

// fp16-accumulate MMA: c/d = 2 x f16x2 regs
#define MMA16816H(c0, c1, a0, a1, a2, a3, b0, b1)                                \
    asm volatile("mma.sync.aligned.m16n8k16.row.col.f16.f16.f16.f16 "            \
                 "{%0,%1}, {%2,%3,%4,%5}, {%6,%7}, {%0,%1};"                      \
                 : "+r"(c0), "+r"(c1)                                             \
                 : "r"(a0), "r"(a1), "r"(a2), "r"(a3), "r"(b0), "r"(b1))

// ------------------------- conversion kernels -------------------------
__global__ void k_convert_x(const float* __restrict__ x) {
    const int id = blockIdx.x * 256 + threadIdx.x;     // 16B output chunks
    const int c  = id & 7;
    const int h  = (id >> 3) & 1;
    const int r  = (id >> 4) & 127;
    const int s  = (id >> 11) & 31;
    const int bm = id >> 16;
    const size_t m = (size_t)bm * 128 + r;
    const size_t k = (size_t)s * 128 + h * 64 + c * 8;

    const float4* src = reinterpret_cast<const float4*>(x + m * KDIM + k);
    float4 v0 = src[0], v1 = src[1];
    __half2 h0 = __floats2half2_rn(v0.x, v0.y);
    __half2 h1 = __floats2half2_rn(v0.z, v0.w);
    __half2 h2 = __floats2half2_rn(v1.x, v1.y);
    __half2 h3 = __floats2half2_rn(v1.z, v1.w);
    uint4 u;
    u.x = *reinterpret_cast<uint32_t*>(&h0);
    u.y = *reinterpret_cast<uint32_t*>(&h1);
    u.z = *reinterpret_cast<uint32_t*>(&h2);
    u.w = *reinterpret_cast<uint32_t*>(&h3);

    const size_t off = (((size_t)(bm * 32 + s) * 128 + r) << 8)
                     + (size_t)(h * 128 + ((c * 16) ^ ((r & 7) << 4)));
    *reinterpret_cast<uint4*>(reinterpret_cast<char*>(g_Xh) + off) = u;
}

__global__ void k_quant_w(const float* __restrict__ w, const float* __restrict__ sc) {
    const int id = blockIdx.x * 256 + threadIdx.x;
    const int c  = id & 7;
    const int h  = (id >> 3) & 1;
    const int r  = (id >> 4) & 255;
    const int s  = (id >> 12) & 31;
    const int bn = id >> 17;
    const size_t o = (size_t)bn * 256 + r;
    const size_t k = (size_t)s * 128 + h * 64 + c * 8;

    const float sv = fmaxf(sc[o * 32 + s], 1e-8f);     // scale group == stage
    const __half hp = __float2half_rn(sv);
    const __half hn = __hneg(hp);

    const float4* src = reinterpret_cast<const float4*>(w + o * KDIM + k);
    float4 v0 = src[0], v1 = src[1];
    __half2 h0 = __halves2half2((v0.x >= 0.f) ? hp : hn, (v0.y >= 0.f) ? hp : hn);
    __half2 h1 = __halves2half2((v0.z >= 0.f) ? hp : hn, (v0.w >= 0.f) ? hp : hn);
    __half2 h2 = __halves2half2((v1.x >= 0.f) ? hp : hn, (v1.y >= 0.f) ? hp : hn);
    __half2 h3 = __halves2half2((v1.z >= 0.f) ? hp : hn, (v1.w >= 0.f) ? hp : hn);
    uint4 u;
    u.x = *reinterpret_cast<uint32_t*>(&h0);
    u.y = *reinterpret_cast<uint32_t*>(&h1);
    u.z = *reinterpret_cast<uint32_t*>(&h2);
    u.w = *reinterpret_cast<uint32_t*>(&h3);

    const size_t off = (((size_t)(bn * 32 + s) * 256 + r) << 8)
                     + (size_t)(h * 128 + ((c * 16) ^ ((r & 7) << 4)));
    *reinterpret_cast<uint4*>(reinterpret_cast<char*>(g_Wh) + off) = u;
}

// ------------------------- GEMM kernel -------------------------
// CTA 128x256, 8 warps 2(M) x 4(N), warp tile 64x64.
// fp16 accumulation within a stage (= one 128-k scale group), spilled to fp32
// accumulators at each stage boundary.
__global__ void __launch_bounds__(256, 1) k_gemm(float* __restrict__ out) {
    extern __shared__ char smem[];
    const uint32_t sb = smem_u32(smem);
    const int tid = threadIdx.x;
    const int wid = tid >> 5;
    const int lane = tid & 31;

    const int bm = blockIdx.x >> 4;              // N-fast: W slab stays L2-resident
    const int bn = blockIdx.x & 15;
    const int wm = wid >> 2;                     // 0..1
    const int wn = wid & 3;                      // 0..3

    const char* gA = reinterpret_cast<const char*>(g_Xh) + (size_t)bm * 32 * A_BYTES;
    const char* gB = reinterpret_cast<const char*>(g_Wh) + (size_t)bn * 32 * B_BYTES;

    auto load_stage = [&](int s) {
        const uint32_t base = sb + (uint32_t)(s & 1) * STAGE_BYTES;
        const char* srcA = gA + (size_t)s * A_BYTES;
        const char* srcB = gB + (size_t)s * B_BYTES;
        #pragma unroll
        for (int i = 0; i < 8; ++i) {
            uint32_t off = (uint32_t)(tid + i * 256) * 16u;
            asm volatile("cp.async.cg.shared.global [%0], [%1], 16;"
                         :: "r"(base + off), "l"(srcA + off) : "memory");
        }
        #pragma unroll
        for (int i = 0; i < 16; ++i) {
            uint32_t off = (uint32_t)(tid + i * 256) * 16u;
            asm volatile("cp.async.cg.shared.global [%0], [%1], 16;"
                         :: "r"(base + A_BYTES + off), "l"(srcB + off) : "memory");
        }
        asm volatile("cp.async.commit_group;" ::: "memory");
    };

    // Fragment addressing (byte offsets within a stage image)
    uint32_t a_row[4], a_swz[4];
    uint32_t b_row[4], b_swz[4];
    const uint32_t a_kl = (uint32_t)((lane >> 4) << 4);
    const uint32_t b_kl = (uint32_t)(((lane >> 3) & 1) << 4);
    #pragma unroll
    for (int mt = 0; mt < 4; ++mt) {
        int row = wm * 64 + mt * 16 + (lane & 15);
        a_row[mt] = (uint32_t)row * 256u;
        a_swz[mt] = (uint32_t)((row & 7) << 4);
    }
    #pragma unroll
    for (int nt = 0; nt < 4; ++nt) {
        int row = wn * 64 + nt * 16 + (lane & 7) + ((lane >> 4) << 3);
        b_row[nt] = (uint32_t)row * 256u;
        b_swz[nt] = (uint32_t)((row & 7) << 4);
    }

    load_stage(0);
    load_stage(1);

    float acc[4][8][4];                           // fp32 running sum
    #pragma unroll
    for (int i = 0; i < 4; ++i)
        #pragma unroll
        for (int j = 0; j < 8; ++j)
            #pragma unroll
            for (int k = 0; k < 4; ++k) acc[i][j][k] = 0.f;

    #pragma unroll 1
    for (int s = 0; s < KSTAGES; ++s) {
        if (s + 1 < KSTAGES)
            asm volatile("cp.async.wait_group 1;" ::: "memory");
        else
            asm volatile("cp.async.wait_group 0;" ::: "memory");
        __syncthreads();

        const uint32_t abase = sb + (uint32_t)(s & 1) * STAGE_BYTES;
        const uint32_t bbase = abase + A_BYTES;

        uint32_t ch[4][8][2];                     // fp16 stage accumulators (f16x2 pairs)
        #pragma unroll
        for (int i = 0; i < 4; ++i)
            #pragma unroll
            for (int j = 0; j < 8; ++j) { ch[i][j][0] = 0u; ch[i][j][1] = 0u; }

        #pragma unroll
        for (int ks = 0; ks < 8; ++ks) {
            const uint32_t hoff = (uint32_t)((ks >> 2) << 7);   // panel 0/128
            const uint32_t kk = (uint32_t)((ks & 3) * 32);
            uint32_t a[4][4], b[4][4];
            #pragma unroll
            for (int mt = 0; mt < 4; ++mt) {
                uint32_t ad = abase + a_row[mt] + hoff + ((kk + a_kl) ^ a_swz[mt]);
                LDMATRIX_X4(a[mt][0], a[mt][1], a[mt][2], a[mt][3], ad);
            }
            #pragma unroll
            for (int nt = 0; nt < 4; ++nt) {
                uint32_t bd = bbase + b_row[nt] + hoff + ((kk + b_kl) ^ b_swz[nt]);
                LDMATRIX_X4(b[nt][0], b[nt][1], b[nt][2], b[nt][3], bd);
            }
            #pragma unroll
            for (int mt = 0; mt < 4; ++mt) {
                #pragma unroll
                for (int nt = 0; nt < 4; ++nt) {
                    MMA16816H(ch[mt][2 * nt][0],     ch[mt][2 * nt][1],
                              a[mt][0], a[mt][1], a[mt][2], a[mt][3], b[nt][0], b[nt][1]);
                    MMA16816H(ch[mt][2 * nt + 1][0], ch[mt][2 * nt + 1][1],
                              a[mt][0], a[mt][1], a[mt][2], a[mt][3], b[nt][2], b[nt][3]);
                }
            }
        }

        // Spill stage (= scale group) partials into fp32 accumulators
        #pragma unroll
        for (int mt = 0; mt < 4; ++mt)
            #pragma unroll
            for (int j = 0; j < 8; ++j) {
                float2 lo = __half22float2(*reinterpret_cast<__half2*>(&ch[mt][j][0]));
                float2 hi = __half22float2(*reinterpret_cast<__half2*>(&ch[mt][j][1]));
                acc[mt][j][0] += lo.x;
                acc[mt][j][1] += lo.y;
                acc[mt][j][2] += hi.x;
                acc[mt][j][3] += hi.y;
            }

        __syncthreads();
        if (s + 2 < KSTAGES) load_stage(s + 2);
    }

    // Epilogue
    {
        const size_t m0 = (size_t)bm * TM;
        const size_t n0 = (size_t)bn * TN;
        const int g = lane >> 2;
        const int tg = lane & 3;
        #pragma unroll
        for (int mt = 0; mt < 4; ++mt) {
            const size_t m = m0 + (size_t)(wm * 64 + mt * 16 + g);
            float* r0 = out + m * NDIM + n0 + wn * 64 + tg * 2;
            float* r1 = r0 + 8 * NDIM;
            #pragma unroll
            for (int j = 0; j < 8; ++j) {
                *reinterpret_cast<float2*>(r0 + j * 8) = make_float2(acc[mt][j][0], acc[mt][j][1]);
                *reinterpret_cast<float2*>(r1 + j * 8) = make_float2(acc[mt][j][2], acc[mt][j][3]);
            }
        }
    }
}

// ------------------------- launch -------------------------
extern "C" void kernel_launch(void* const* d_in, const int* in_sizes, int n_in,
                              void* d_out, int out_size) {
    const float* x = nullptr;
    const float* w = nullptr;
    const float* sc = nullptr;
    for (int i = 0; i < n_in; ++i) {
        if (in_sizes[i] == MDIM * KDIM) x = (const float*)d_in[i];
        else if (in_sizes[i] == NDIM * KDIM) w = (const float*)d_in[i];
        else if (in_sizes[i] == NDIM * (KDIM / 128)) sc = (const float*)d_in[i];
    }
    float* out = (float*)d_out;

    cudaFuncSetAttribute(k_gemm, cudaFuncAttributeMaxDynamicSharedMemorySize, SMEM_BYTES);

    k_convert_x<<<MDIM * KDIM * 2 / 16 / 256, 256>>>(x);
    k_quant_w<<<NDIM * KDIM * 2 / 16 / 256, 256>>>(w, sc);
    k_gemm<<<(MDIM / TM) * (NDIM / TN), 256, SMEM_BYTES>>>(out);
}

// round 5
// speedup vs baseline: 1.1451x; 1.1451x over previous
#include <cuda_runtime.h>
#include <cuda_fp16.h>
#include <cstdint>

// out[M,N] = X[M,K] @ Wq[N,K]^T, Wq = sign(W)*max(scales,1e-8), groups of 128 along K
#define MDIM 8192
#define NDIM 4096
#define KDIM 4096

#define TM 128
#define TN 256
#define TKH 128                      // halves per K stage (two 64-half panels)
#define NSTAGE 2
#define KSTAGES (KDIM / TKH)         // 32

#define A_BYTES (TM * 256)           // 32768 per stage
#define B_BYTES (TN * 256)           // 65536 per stage
#define STAGE_BYTES (A_BYTES + B_BYTES)        // 98304
#define SMEM_BYTES (NSTAGE * STAGE_BYTES)      // 196608

#define NTHREADS 512

// Pre-swizzled tile-major operand images (exact smem byte image per (tile,stage)).
__device__ __align__(16) __half g_Xh[(size_t)MDIM * KDIM];   // 64 MB
__device__ __align__(16) __half g_Wh[(size_t)NDIM * KDIM];   // 32 MB

__device__ __forceinline__ uint32_t smem_u32(const void* p) {
    uint32_t a;
    asm("{ .reg .u64 t; cvta.to.shared.u64 t, %1; cvt.u32.u64 %0, t; }" : "=r"(a) : "l"(p));
    return a;
}

#define LDMATRIX_X4(r0, r1, r2, r3, addr)                                        \
    asm volatile("ldmatrix.sync.aligned.m8n8.x4.shared.b16 {%0,%1,%2,%3}, [%4];" \
                 : "=r"(r0), "=r"(r1), "=r"(r2), "=r"(r3) : "r"(addr))

#define MMA16816(c, a0, a1, a2, a3, b0, b1)                                      \
    asm volatile("mma.sync.aligned.m16n8k16.row.col.f32.f16.f16.f32 "            \
                 "{%0,%1,%2,%3}, {%4,%5,%6,%7}, {%8,%9}, {%0,%1,%2,%3};"         \
                 : "+f"((c)[0]), "+f"((c)[1]), "+f"((c)[2]), "+f"((c)[3])        \
                 : "r"(a0), "r"(a1), "r"(a2), "r"(a3), "r"(b0), "r"(b1))

// ------------------------- conversion kernels -------------------------
__global__ void k_convert_x(const float* __restrict__ x) {
    const int id = blockIdx.x * 256 + threadIdx.x;     // 16B output chunks
    const int c  = id & 7;
    const int h  = (id >> 3) & 1;
    const int r  = (id >> 4) & 127;
    const int s  = (id >> 11) & 31;
    const int bm = id >> 16;
    const size_t m = (size_t)bm * 128 + r;
    const size_t k = (size_t)s * 128 + h * 64 + c * 8;

    const float4* src = reinterpret_cast<const float4*>(x + m * KDIM + k);
    float4 v0 = src[0], v1 = src[1];
    __half2 h0 = __floats2half2_rn(v0.x, v0.y);
    __half2 h1 = __floats2half2_rn(v0.z, v0.w);
    __half2 h2 = __floats2half2_rn(v1.x, v1.y);
    __half2 h3 = __floats2half2_rn(v1.z, v1.w);
    uint4 u;
    u.x = *reinterpret_cast<uint32_t*>(&h0);
    u.y = *reinterpret_cast<uint32_t*>(&h1);
    u.z = *reinterpret_cast<uint32_t*>(&h2);
    u.w = *reinterpret_cast<uint32_t*>(&h3);

    const size_t off = (((size_t)(bm * 32 + s) * 128 + r) << 8)
                     + (size_t)(h * 128 + ((c * 16) ^ ((r & 7) << 4)));
    *reinterpret_cast<uint4*>(reinterpret_cast<char*>(g_Xh) + off) = u;
}

__global__ void k_quant_w(const float* __restrict__ w, const float* __restrict__ sc) {
    const int id = blockIdx.x * 256 + threadIdx.x;
    const int c  = id & 7;
    const int h  = (id >> 3) & 1;
    const int r  = (id >> 4) & 255;
    const int s  = (id >> 12) & 31;
    const int bn = id >> 17;
    const size_t o = (size_t)bn * 256 + r;
    const size_t k = (size_t)s * 128 + h * 64 + c * 8;

    const float sv = fmaxf(sc[o * 32 + s], 1e-8f);     // scale group == stage
    const __half hp = __float2half_rn(sv);
    const __half hn = __hneg(hp);

    const float4* src = reinterpret_cast<const float4*>(w + o * KDIM + k);
    float4 v0 = src[0], v1 = src[1];
    __half2 h0 = __halves2half2((v0.x >= 0.f) ? hp : hn, (v0.y >= 0.f) ? hp : hn);
    __half2 h1 = __halves2half2((v0.z >= 0.f) ? hp : hn, (v0.w >= 0.f) ? hp : hn);
    __half2 h2 = __halves2half2((v1.x >= 0.f) ? hp : hn, (v1.y >= 0.f) ? hp : hn);
    __half2 h3 = __halves2half2((v1.z >= 0.f) ? hp : hn, (v1.w >= 0.f) ? hp : hn);
    uint4 u;
    u.x = *reinterpret_cast<uint32_t*>(&h0);
    u.y = *reinterpret_cast<uint32_t*>(&h1);
    u.z = *reinterpret_cast<uint32_t*>(&h2);
    u.w = *reinterpret_cast<uint32_t*>(&h3);

    const size_t off = (((size_t)(bn * 32 + s) * 256 + r) << 8)
                     + (size_t)(h * 128 + ((c * 16) ^ ((r & 7) << 4)));
    *reinterpret_cast<uint4*>(reinterpret_cast<char*>(g_Wh) + off) = u;
}

// ------------------------- GEMM kernel -------------------------
// CTA 128x256, 512 threads, 16 warps 4(M) x 4(N), warp tile 32x64.
// 4 warps per SMSP hide LDSM latency; fp32-accum HMMA.
__global__ void __launch_bounds__(NTHREADS, 1) k_gemm(float* __restrict__ out) {
    extern __shared__ char smem[];
    const uint32_t sb = smem_u32(smem);
    const int tid = threadIdx.x;
    const int wid = tid >> 5;
    const int lane = tid & 31;

    const int bm = blockIdx.x >> 4;              // N-fast: W slab stays L2-resident
    const int bn = blockIdx.x & 15;
    const int wm = wid >> 2;                     // 0..3 (M row-group of 32)
    const int wn = wid & 3;                      // 0..3 (N col-group of 64)

    const char* gA = reinterpret_cast<const char*>(g_Xh) + (size_t)bm * 32 * A_BYTES;
    const char* gB = reinterpret_cast<const char*>(g_Wh) + (size_t)bn * 32 * B_BYTES;

    auto load_stage = [&](int s) {
        const uint32_t base = sb + (uint32_t)(s & 1) * STAGE_BYTES;
        const char* srcA = gA + (size_t)s * A_BYTES;
        const char* srcB = gB + (size_t)s * B_BYTES;
        #pragma unroll
        for (int i = 0; i < 4; ++i) {
            uint32_t off = (uint32_t)(tid + i * NTHREADS) * 16u;
            asm volatile("cp.async.cg.shared.global [%0], [%1], 16;"
                         :: "r"(base + off), "l"(srcA + off) : "memory");
        }
        #pragma unroll
        for (int i = 0; i < 8; ++i) {
            uint32_t off = (uint32_t)(tid + i * NTHREADS) * 16u;
            asm volatile("cp.async.cg.shared.global [%0], [%1], 16;"
                         :: "r"(base + A_BYTES + off), "l"(srcB + off) : "memory");
        }
        asm volatile("cp.async.commit_group;" ::: "memory");
    };

    // Fragment addressing (byte offsets within a stage image)
    uint32_t a_row[2], a_swz[2];
    uint32_t b_row[4], b_swz[4];
    const uint32_t a_kl = (uint32_t)((lane >> 4) << 4);
    const uint32_t b_kl = (uint32_t)(((lane >> 3) & 1) << 4);
    #pragma unroll
    for (int mt = 0; mt < 2; ++mt) {
        int row = wm * 32 + mt * 16 + (lane & 15);
        a_row[mt] = (uint32_t)row * 256u;
        a_swz[mt] = (uint32_t)((row & 7) << 4);
    }
    #pragma unroll
    for (int nt = 0; nt < 4; ++nt) {
        int row = wn * 64 + nt * 16 + (lane & 7) + ((lane >> 4) << 3);
        b_row[nt] = (uint32_t)row * 256u;
        b_swz[nt] = (uint32_t)((row & 7) << 4);
    }

    load_stage(0);
    load_stage(1);

    float acc[2][8][4];
    #pragma unroll
    for (int i = 0; i < 2; ++i)
        #pragma unroll
        for (int j = 0; j < 8; ++j)
            #pragma unroll
            for (int k = 0; k < 4; ++k) acc[i][j][k] = 0.f;

    #pragma unroll 1
    for (int s = 0; s < KSTAGES; ++s) {
        if (s + 1 < KSTAGES)
            asm volatile("cp.async.wait_group 1;" ::: "memory");
        else
            asm volatile("cp.async.wait_group 0;" ::: "memory");
        __syncthreads();

        const uint32_t abase = sb + (uint32_t)(s & 1) * STAGE_BYTES;
        const uint32_t bbase = abase + A_BYTES;

        #pragma unroll
        for (int ks = 0; ks < 8; ++ks) {
            const uint32_t hoff = (uint32_t)((ks >> 2) << 7);   // panel 0/128
            const uint32_t kk = (uint32_t)((ks & 3) * 32);
            uint32_t a[2][4], b[4][4];
            #pragma unroll
            for (int mt = 0; mt < 2; ++mt) {
                uint32_t ad = abase + a_row[mt] + hoff + ((kk + a_kl) ^ a_swz[mt]);
                LDMATRIX_X4(a[mt][0], a[mt][1], a[mt][2], a[mt][3], ad);
            }
            #pragma unroll
            for (int nt = 0; nt < 4; ++nt) {
                uint32_t bd = bbase + b_row[nt] + hoff + ((kk + b_kl) ^ b_swz[nt]);
                LDMATRIX_X4(b[nt][0], b[nt][1], b[nt][2], b[nt][3], bd);
            }
            #pragma unroll
            for (int mt = 0; mt < 2; ++mt) {
                #pragma unroll
                for (int nt = 0; nt < 4; ++nt) {
                    MMA16816(acc[mt][2 * nt],     a[mt][0], a[mt][1], a[mt][2], a[mt][3],
                             b[nt][0], b[nt][1]);
                    MMA16816(acc[mt][2 * nt + 1], a[mt][0], a[mt][1], a[mt][2], a[mt][3],
                             b[nt][2], b[nt][3]);
                }
            }
        }

        __syncthreads();
        if (s + 2 < KSTAGES) load_stage(s + 2);
    }

    // Epilogue: direct gmem stores
    {
        const size_t m0 = (size_t)bm * TM;
        const size_t n0 = (size_t)bn * TN;
        const int g = lane >> 2;
        const int tg = lane & 3;
        #pragma unroll
        for (int mt = 0; mt < 2; ++mt) {
            const size_t m = m0 + (size_t)(wm * 32 + mt * 16 + g);
            float* r0 = out + m * NDIM + n0 + wn * 64 + tg * 2;
            float* r1 = r0 + 8 * NDIM;
            #pragma unroll
            for (int j = 0; j < 8; ++j) {
                *reinterpret_cast<float2*>(r0 + j * 8) = make_float2(acc[mt][j][0], acc[mt][j][1]);
                *reinterpret_cast<float2*>(r1 + j * 8) = make_float2(acc[mt][j][2], acc[mt][j][3]);
            }
        }
    }
}

// ------------------------- launch -------------------------
extern "C" void kernel_launch(void* const* d_in, const int* in_sizes, int n_in,
                              void* d_out, int out_size) {
    const float* x = nullptr;
    const float* w = nullptr;
    const float* sc = nullptr;
    for (int i = 0; i < n_in; ++i) {
        if (in_sizes[i] == MDIM * KDIM) x = (const float*)d_in[i];
        else if (in_sizes[i] == NDIM * KDIM) w = (const float*)d_in[i];
        else if (in_sizes[i] == NDIM * (KDIM / 128)) sc = (const float*)d_in[i];
    }
    float* out = (float*)d_out;

    cudaFuncSetAttribute(k_gemm, cudaFuncAttributeMaxDynamicSharedMemorySize, SMEM_BYTES);

    k_convert_x<<<MDIM * KDIM * 2 / 16 / 256, 256>>>(x);
    k_quant_w<<<NDIM * KDIM * 2 / 16 / 256, 256>>>(w, sc);
    k_gemm<<<(MDIM / TM) * (NDIM / TN), NTHREADS, SMEM_BYTES>>>(out);
}